// round 10
// baseline (speedup 1.0000x reference)
#include <cuda_runtime.h>

// LSTM: B=32768, T=28, IN=28, H=8, gates i,j,f,o (cols 0-7,8-15,16-23,24-31).
// R10 = R9 (weights-in-registers, lane q owns gate-col pair (q,q+16), K-axis
// f32x2, 2 elems/warp, x staged once into smem) + occupancy 3 -> 4 CTAs/SM:
// regs are 126, so launch_bounds(128,4) caps at 128 with zero spill and
// gives 4 warps/SMSP (+33% latency cover of the ~240cyc serial step path).

#define T_STEPS 28
#define IN_DIM 28
#define NH 8
#define NC 10
#define TPB 128
#define ELEMS_PER_CTA 8                       // TPB/32 warps * 2 elems
#define X_FLOATS_PER_ELEM (T_STEPS * IN_DIM)  // 784
#define X_F4_PER_CTA (ELEMS_PER_CTA * X_FLOATS_PER_ELEM / 4)  // 1568

typedef unsigned long long u64;

__device__ __forceinline__ u64 pack2(float lo, float hi) {
    u64 r;
    asm("mov.b64 %0, {%1, %2};" : "=l"(r) : "f"(lo), "f"(hi));
    return r;
}
__device__ __forceinline__ void unpack2(u64 v, float& lo, float& hi) {
    asm("mov.b64 {%0, %1}, %2;" : "=f"(lo), "=f"(hi) : "l"(v));
}
__device__ __forceinline__ u64 fma2(u64 a, u64 b, u64 c) {
    u64 d;
    asm("fma.rn.f32x2 %0, %1, %2, %3;" : "=l"(d) : "l"(a), "l"(b), "l"(c));
    return d;
}
__device__ __forceinline__ float rcp_fast(float x) {
    float r;
    asm("rcp.approx.ftz.f32 %0, %1;" : "=f"(r) : "f"(x));
    return r;
}
__device__ __forceinline__ float ex2_fast(float x) {
    float r;
    asm("ex2.approx.ftz.f32 %0, %1;" : "=f"(r) : "f"(x));
    return r;
}

#define LOG2E 1.4426950408889634f

__device__ __forceinline__ float sigmoid_f(float x) {
    return rcp_fast(1.0f + ex2_fast(-x * LOG2E));
}
__device__ __forceinline__ float tanh_f(float x) {
    return 1.0f - 2.0f * rcp_fast(1.0f + ex2_fast(2.0f * LOG2E * x));
}

__global__ void __launch_bounds__(TPB, 4)   // 128-reg cap (used: 126), 4 CTAs/SM
lstm_kernel(const float* __restrict__ x,
            const float* __restrict__ W,     // [36, 32] row-major
            const float* __restrict__ b,     // [32]
            const float* __restrict__ ow,    // [8, 10]
            const float* __restrict__ ob,    // [10]
            float* __restrict__ out,         // [B, 10]
            int B)
{
    __shared__ __align__(16) float sX[ELEMS_PER_CTA * X_FLOATS_PER_ELEM];

    const int tid = threadIdx.x;

    // ---- bulk-stage this CTA's x: 25KB, fully coalesced, deep MLP ----
    {
        const float4* __restrict__ gx = reinterpret_cast<const float4*>(
            x + (size_t)blockIdx.x * ELEMS_PER_CTA * X_FLOATS_PER_ELEM);
        float4* sx4 = reinterpret_cast<float4*>(sX);
#pragma unroll
        for (int i = 0; i < X_F4_PER_CTA / TPB; i++)
            sx4[i * TPB + tid] = gx[i * TPB + tid];
        // remainder: 1568 = 12*128 + 32
        if (tid < X_F4_PER_CTA - (X_F4_PER_CTA / TPB) * TPB)
            sx4[(X_F4_PER_CTA / TPB) * TPB + tid] =
                gx[(X_F4_PER_CTA / TPB) * TPB + tid];
    }

    const int lid  = tid & 31;
    const int q    = lid & 15;                 // lane within half-warp
    const int elem_local = (tid >> 5) * 2 + (lid >> 4);
    const int elem = blockIdx.x * ELEMS_PER_CTA + elem_local;

    // ---- weight column pair (q, q+16): 18 K-pairs each, in registers ----
    u64 wA[18], wB[18];
#pragma unroll
    for (int m = 0; m < 18; m++) {
        wA[m] = pack2(W[(2 * m) * 32 + q],      W[(2 * m + 1) * 32 + q]);
        wB[m] = pack2(W[(2 * m) * 32 + q + 16], W[(2 * m + 1) * 32 + q + 16]);
    }
    // bias seeds; FORGET_BIAS baked into f-column (q<8)
    const u64 accA0 = pack2(b[q], 0.0f);
    const u64 accB0 = pack2(b[q + 16] + (q < 8 ? 1.0f : 0.0f), 0.0f);

    // A-column activation select: q<8 -> sigmoid(i), q>=8 -> tanh(j)
    const bool ij = (q < 8);
    const float Ca = ij ? -LOG2E : 2.0f * LOG2E;
    const float Aa = ij ? 0.0f : 1.0f;
    const float Ba = ij ? 1.0f : -2.0f;

    __syncthreads();   // staging complete

    if (elem >= B) return;

    const ulonglong2* __restrict__ xs = reinterpret_cast<const ulonglong2*>(
        sX + elem_local * X_FLOATS_PER_ELEM);

    u64 hp[4];                      // h as 4 packed pairs (h0,h1)..(h6,h7)
#pragma unroll
    for (int m = 0; m < 4; m++) hp[m] = 0ull;
    float c = 0.0f;                 // cell state (valid on lanes q<8)

#pragma unroll 1
    for (int t = 0; t < T_STEPS; t++) {
        // x from smem: 7 LDS.128 broadcast (2 distinct addrs/warp), lat 29
        ulonglong2 xv0 = xs[t * 7 + 0];
        ulonglong2 xv1 = xs[t * 7 + 1];
        ulonglong2 xv2 = xs[t * 7 + 2];
        ulonglong2 xv3 = xs[t * 7 + 3];
        ulonglong2 xv4 = xs[t * 7 + 4];
        ulonglong2 xv5 = xs[t * 7 + 5];
        ulonglong2 xv6 = xs[t * 7 + 6];

        u64 accA = accA0, accB = accB0;
        accA = fma2(xv0.x, wA[0],  accA); accB = fma2(xv0.x, wB[0],  accB);
        accA = fma2(xv0.y, wA[1],  accA); accB = fma2(xv0.y, wB[1],  accB);
        accA = fma2(xv1.x, wA[2],  accA); accB = fma2(xv1.x, wB[2],  accB);
        accA = fma2(xv1.y, wA[3],  accA); accB = fma2(xv1.y, wB[3],  accB);
        accA = fma2(xv2.x, wA[4],  accA); accB = fma2(xv2.x, wB[4],  accB);
        accA = fma2(xv2.y, wA[5],  accA); accB = fma2(xv2.y, wB[5],  accB);
        accA = fma2(xv3.x, wA[6],  accA); accB = fma2(xv3.x, wB[6],  accB);
        accA = fma2(xv3.y, wA[7],  accA); accB = fma2(xv3.y, wB[7],  accB);
        accA = fma2(xv4.x, wA[8],  accA); accB = fma2(xv4.x, wB[8],  accB);
        accA = fma2(xv4.y, wA[9],  accA); accB = fma2(xv4.y, wB[9],  accB);
        accA = fma2(xv5.x, wA[10], accA); accB = fma2(xv5.x, wB[10], accB);
        accA = fma2(xv5.y, wA[11], accA); accB = fma2(xv5.y, wB[11], accB);
        accA = fma2(xv6.x, wA[12], accA); accB = fma2(xv6.x, wB[12], accB);
        accA = fma2(xv6.y, wA[13], accA); accB = fma2(xv6.y, wB[13], accB);
        // h contribution last
        accA = fma2(hp[0], wA[14], accA); accB = fma2(hp[0], wB[14], accB);
        accA = fma2(hp[1], wA[15], accA); accB = fma2(hp[1], wB[15], accB);
        accA = fma2(hp[2], wA[16], accA); accB = fma2(hp[2], wB[16], accB);
        accA = fma2(hp[3], wA[17], accA); accB = fma2(hp[3], wB[17], accB);

        // horizontal reduce: gate = lo + hi
        float alo, ahi, blo, bhi;
        unpack2(accA, alo, ahi);
        unpack2(accB, blo, bhi);
        float gA = alo + ahi;
        float gB = blo + bhi;

        // activations; B-column (f or o) is always sigmoid
        float actA = Aa + Ba * rcp_fast(1.0f + ex2_fast(Ca * gA));
        float actB = sigmoid_f(gB);

        // lanes q<8 gather partner's (tanh(j), sig(o)) from lane q+8
        float pA = __shfl_down_sync(0xffffffffu, actA, 8, 16);
        float pB = __shfl_down_sync(0xffffffffu, actB, 8, 16);

        // state update (valid on q<8): is=actA, fs=actB, jt=pA, os=pB
        float cn = c * actB + actA * pA;
        c = cn;
        float h = tanh_f(cn) * pB;

        // broadcast h_0..h_7 to all 16 lanes of this half, repack as pairs
        float h0 = __shfl_sync(0xffffffffu, h, 0, 16);
        float h1 = __shfl_sync(0xffffffffu, h, 1, 16);
        float h2 = __shfl_sync(0xffffffffu, h, 2, 16);
        float h3 = __shfl_sync(0xffffffffu, h, 3, 16);
        float h4 = __shfl_sync(0xffffffffu, h, 4, 16);
        float h5 = __shfl_sync(0xffffffffu, h, 5, 16);
        float h6 = __shfl_sync(0xffffffffu, h, 6, 16);
        float h7 = __shfl_sync(0xffffffffu, h, 7, 16);
        hp[0] = pack2(h0, h1);
        hp[1] = pack2(h2, h3);
        hp[2] = pack2(h4, h5);
        hp[3] = pack2(h6, h7);
    }

    // output projection: lane q (<10) computes class q for its element
    if (q < NC) {
        float h0, h1, h2, h3, h4, h5, h6, h7;
        unpack2(hp[0], h0, h1);
        unpack2(hp[1], h2, h3);
        unpack2(hp[2], h4, h5);
        unpack2(hp[3], h6, h7);
        float a = ob[q];
        a += h0 * ow[0 * NC + q];
        a += h1 * ow[1 * NC + q];
        a += h2 * ow[2 * NC + q];
        a += h3 * ow[3 * NC + q];
        a += h4 * ow[4 * NC + q];
        a += h5 * ow[5 * NC + q];
        a += h6 * ow[6 * NC + q];
        a += h7 * ow[7 * NC + q];
        out[(size_t)elem * NC + q] = a;
    }
}

extern "C" void kernel_launch(void* const* d_in, const int* in_sizes, int n_in,
                              void* d_out, int out_size) {
    const float* x  = (const float*)d_in[0];
    const float* W  = (const float*)d_in[1];
    const float* b  = (const float*)d_in[2];
    const float* ow = (const float*)d_in[3];
    const float* ob = (const float*)d_in[4];
    float* out = (float*)d_out;

    const int B = in_sizes[0] / (T_STEPS * IN_DIM);
    const int grid = (B + ELEMS_PER_CTA - 1) / ELEMS_PER_CTA;
    lstm_kernel<<<grid, TPB>>>(x, W, b, ow, ob, out, B);
}

// round 11
// speedup vs baseline: 1.0525x; 1.0525x over previous
#include <cuda_runtime.h>

// LSTM: B=32768, T=28, IN=28, H=8, gates i,j,f,o (cols 0-7,8-15,16-23,24-31).
// R11 = R10 (weights-in-registers, lane q owns gate-col pair (q,q+16), K-axis
// f32x2, 2 elems/warp, x staged in smem) with the h-broadcast restructured:
// 8x shfl + 4x pack  ->  1 predicated STS + syncwarp + 2x LDS.128 (pairs come
// back pre-packed). Cuts ~12 instr/step/warp and unloads the SHFL pipe
// (R10 accounting: 10 shfl of ~75 instr/step; issue 46%, fma 44%).

#define T_STEPS 28
#define IN_DIM 28
#define NH 8
#define NC 10
#define TPB 128
#define ELEMS_PER_CTA 8                       // TPB/32 warps * 2 elems
#define X_FLOATS_PER_ELEM (T_STEPS * IN_DIM)  // 784
#define X_F4_PER_CTA (ELEMS_PER_CTA * X_FLOATS_PER_ELEM / 4)  // 1568

typedef unsigned long long u64;

__device__ __forceinline__ u64 pack2(float lo, float hi) {
    u64 r;
    asm("mov.b64 %0, {%1, %2};" : "=l"(r) : "f"(lo), "f"(hi));
    return r;
}
__device__ __forceinline__ void unpack2(u64 v, float& lo, float& hi) {
    asm("mov.b64 {%0, %1}, %2;" : "=f"(lo), "=f"(hi) : "l"(v));
}
__device__ __forceinline__ u64 fma2(u64 a, u64 b, u64 c) {
    u64 d;
    asm("fma.rn.f32x2 %0, %1, %2, %3;" : "=l"(d) : "l"(a), "l"(b), "l"(c));
    return d;
}
__device__ __forceinline__ float rcp_fast(float x) {
    float r;
    asm("rcp.approx.ftz.f32 %0, %1;" : "=f"(r) : "f"(x));
    return r;
}
__device__ __forceinline__ float ex2_fast(float x) {
    float r;
    asm("ex2.approx.ftz.f32 %0, %1;" : "=f"(r) : "f"(x));
    return r;
}

#define LOG2E 1.4426950408889634f

__device__ __forceinline__ float sigmoid_f(float x) {
    return rcp_fast(1.0f + ex2_fast(-x * LOG2E));
}
__device__ __forceinline__ float tanh_f(float x) {
    return 1.0f - 2.0f * rcp_fast(1.0f + ex2_fast(2.0f * LOG2E * x));
}

__global__ void __launch_bounds__(TPB, 4)
lstm_kernel(const float* __restrict__ x,
            const float* __restrict__ W,     // [36, 32] row-major
            const float* __restrict__ b,     // [32]
            const float* __restrict__ ow,    // [8, 10]
            const float* __restrict__ ob,    // [10]
            float* __restrict__ out,         // [B, 10]
            int B)
{
    __shared__ __align__(16) float sX[ELEMS_PER_CTA * X_FLOATS_PER_ELEM];
    __shared__ __align__(16) float sH[ELEMS_PER_CTA * NH];   // h exchange

    const int tid = threadIdx.x;

    // ---- bulk-stage this CTA's x: 25KB, fully coalesced, deep MLP ----
    {
        const float4* __restrict__ gx = reinterpret_cast<const float4*>(
            x + (size_t)blockIdx.x * ELEMS_PER_CTA * X_FLOATS_PER_ELEM);
        float4* sx4 = reinterpret_cast<float4*>(sX);
#pragma unroll
        for (int i = 0; i < X_F4_PER_CTA / TPB; i++)
            sx4[i * TPB + tid] = gx[i * TPB + tid];
        // remainder: 1568 = 12*128 + 32
        if (tid < X_F4_PER_CTA - (X_F4_PER_CTA / TPB) * TPB)
            sx4[(X_F4_PER_CTA / TPB) * TPB + tid] =
                gx[(X_F4_PER_CTA / TPB) * TPB + tid];
    }

    const int lid  = tid & 31;
    const int q    = lid & 15;                 // lane within half-warp
    const int elem_local = (tid >> 5) * 2 + (lid >> 4);
    const int elem = blockIdx.x * ELEMS_PER_CTA + elem_local;

    // ---- weight column pair (q, q+16): 18 K-pairs each, in registers ----
    u64 wA[18], wB[18];
#pragma unroll
    for (int m = 0; m < 18; m++) {
        wA[m] = pack2(W[(2 * m) * 32 + q],      W[(2 * m + 1) * 32 + q]);
        wB[m] = pack2(W[(2 * m) * 32 + q + 16], W[(2 * m + 1) * 32 + q + 16]);
    }
    // bias seeds; FORGET_BIAS baked into f-column (q<8)
    const u64 accA0 = pack2(b[q], 0.0f);
    const u64 accB0 = pack2(b[q + 16] + (q < 8 ? 1.0f : 0.0f), 0.0f);

    // A-column activation select: q<8 -> sigmoid(i), q>=8 -> tanh(j)
    const bool ij = (q < 8);
    const float Ca = ij ? -LOG2E : 2.0f * LOG2E;
    const float Aa = ij ? 0.0f : 1.0f;
    const float Ba = ij ? 1.0f : -2.0f;

    __syncthreads();   // staging complete

    if (elem >= B) return;

    const ulonglong2* __restrict__ xs = reinterpret_cast<const ulonglong2*>(
        sX + elem_local * X_FLOATS_PER_ELEM);
    const ulonglong2* __restrict__ hv = reinterpret_cast<const ulonglong2*>(
        sH + elem_local * NH);

    // h as 2 ulonglong2 = 4 packed pairs (h0,h1)..(h6,h7)
    ulonglong2 hp01, hp23;
    hp01.x = 0ull; hp01.y = 0ull; hp23.x = 0ull; hp23.y = 0ull;
    float c = 0.0f;                 // cell state (valid on lanes q<8)

#pragma unroll 1
    for (int t = 0; t < T_STEPS; t++) {
        // x from smem: 7 LDS.128 broadcast (2 distinct addrs/warp), lat 29
        ulonglong2 xv0 = xs[t * 7 + 0];
        ulonglong2 xv1 = xs[t * 7 + 1];
        ulonglong2 xv2 = xs[t * 7 + 2];
        ulonglong2 xv3 = xs[t * 7 + 3];
        ulonglong2 xv4 = xs[t * 7 + 4];
        ulonglong2 xv5 = xs[t * 7 + 5];
        ulonglong2 xv6 = xs[t * 7 + 6];

        u64 accA = accA0, accB = accB0;
        accA = fma2(xv0.x, wA[0],  accA); accB = fma2(xv0.x, wB[0],  accB);
        accA = fma2(xv0.y, wA[1],  accA); accB = fma2(xv0.y, wB[1],  accB);
        accA = fma2(xv1.x, wA[2],  accA); accB = fma2(xv1.x, wB[2],  accB);
        accA = fma2(xv1.y, wA[3],  accA); accB = fma2(xv1.y, wB[3],  accB);
        accA = fma2(xv2.x, wA[4],  accA); accB = fma2(xv2.x, wB[4],  accB);
        accA = fma2(xv2.y, wA[5],  accA); accB = fma2(xv2.y, wB[5],  accB);
        accA = fma2(xv3.x, wA[6],  accA); accB = fma2(xv3.x, wB[6],  accB);
        accA = fma2(xv3.y, wA[7],  accA); accB = fma2(xv3.y, wB[7],  accB);
        accA = fma2(xv4.x, wA[8],  accA); accB = fma2(xv4.x, wB[8],  accB);
        accA = fma2(xv4.y, wA[9],  accA); accB = fma2(xv4.y, wB[9],  accB);
        accA = fma2(xv5.x, wA[10], accA); accB = fma2(xv5.x, wB[10], accB);
        accA = fma2(xv5.y, wA[11], accA); accB = fma2(xv5.y, wB[11], accB);
        accA = fma2(xv6.x, wA[12], accA); accB = fma2(xv6.x, wB[12], accB);
        accA = fma2(xv6.y, wA[13], accA); accB = fma2(xv6.y, wB[13], accB);
        // h contribution last (pairs straight from LDS.128)
        accA = fma2(hp01.x, wA[14], accA); accB = fma2(hp01.x, wB[14], accB);
        accA = fma2(hp01.y, wA[15], accA); accB = fma2(hp01.y, wB[15], accB);
        accA = fma2(hp23.x, wA[16], accA); accB = fma2(hp23.x, wB[16], accB);
        accA = fma2(hp23.y, wA[17], accA); accB = fma2(hp23.y, wB[17], accB);

        // horizontal reduce: gate = lo + hi
        float alo, ahi, blo, bhi;
        unpack2(accA, alo, ahi);
        unpack2(accB, blo, bhi);
        float gA = alo + ahi;
        float gB = blo + bhi;

        // activations; B-column (f or o) is always sigmoid
        float actA = Aa + Ba * rcp_fast(1.0f + ex2_fast(Ca * gA));
        float actB = sigmoid_f(gB);

        // lanes q<8 gather partner's (tanh(j), sig(o)) from lane q+8
        float pA = __shfl_down_sync(0xffffffffu, actA, 8, 16);
        float pB = __shfl_down_sync(0xffffffffu, actB, 8, 16);

        // state update (valid on q<8): is=actA, fs=actB, jt=pA, os=pB
        float cn = c * actB + actA * pA;
        c = cn;
        float h = tanh_f(cn) * pB;

        // h exchange via smem: 8 owner lanes store, all lanes reload packed
        if (q < 8) sH[elem_local * NH + q] = h;
        __syncwarp();
        hp01 = hv[0];        // (h0,h1),(h2,h3)
        hp23 = hv[1];        // (h4,h5),(h6,h7)
        __syncwarp();        // reads done before next iter's stores
    }

    // output projection: lane q (<10) computes class q for its element
    if (q < NC) {
        float h0, h1, h2, h3, h4, h5, h6, h7;
        unpack2(hp01.x, h0, h1);
        unpack2(hp01.y, h2, h3);
        unpack2(hp23.x, h4, h5);
        unpack2(hp23.y, h6, h7);
        float a = ob[q];
        a += h0 * ow[0 * NC + q];
        a += h1 * ow[1 * NC + q];
        a += h2 * ow[2 * NC + q];
        a += h3 * ow[3 * NC + q];
        a += h4 * ow[4 * NC + q];
        a += h5 * ow[5 * NC + q];
        a += h6 * ow[6 * NC + q];
        a += h7 * ow[7 * NC + q];
        out[(size_t)elem * NC + q] = a;
    }
}

extern "C" void kernel_launch(void* const* d_in, const int* in_sizes, int n_in,
                              void* d_out, int out_size) {
    const float* x  = (const float*)d_in[0];
    const float* W  = (const float*)d_in[1];
    const float* b  = (const float*)d_in[2];
    const float* ow = (const float*)d_in[3];
    const float* ob = (const float*)d_in[4];
    float* out = (float*)d_out;

    const int B = in_sizes[0] / (T_STEPS * IN_DIM);
    const int grid = (B + ELEMS_PER_CTA - 1) / ELEMS_PER_CTA;
    lstm_kernel<<<grid, TPB>>>(x, W, b, ow, ob, out, B);
}